// round 15
// baseline (speedup 1.0000x reference)
#include <cuda_runtime.h>
#include <cuda_fp16.h>
#include <cstdint>

// ============================================================================
// InterpNet via mma.sync HMMA, single fp16 term, fp32 accumulate.
// Round 13: 72KB k=128 weight stages (6/tile), ring of 2, XOR-swizzled A
// (SA=512, no padding), SW=72 weight rows. Persistent CTAs.
// ============================================================================

#define THREADS 256
#define TILE_M  128
#define SW      72            // W smem row stride (64B data + 8B pad, conflict-free)
#define SUBCH   18432         // one k=32 slab: 256 rows x SW
#define STB     73728         // stage = 4 slabs = k=128
#define NST     6             // stages per tile (2 per layer)
#define NSUB    24            // k=32 slabs in g_wpack
#define NSRC_MAX 100000

// smem offsets
#define OFF_AH    0           // fp16 A [128][256], 512B rows, XOR swizzle   65536
#define OFF_W     65536       // W ring 2 x 73728                          147456
#define OFF_BIAS  212992      // f32[3][256]
#define OFF_WP    216064      // f32[3][256]
#define OFF_WOUT  219136      // f32[256]
#define OFF_POS   220160      // f32[3][128]
#define OFF_RED   221696      // f32[128][4]
#define SMEM_TOTAL 223744

__device__ __align__(16) unsigned char g_wpack[NSUB * SUBCH];             // 442 KB
__device__ __align__(16) unsigned char g_latpack[(size_t)NSRC_MAX * 512]; // 51.2 MB

// ---------------- helpers ---------------------------------------------------
__device__ __forceinline__ uint32_t smem_u32(const void* p) {
    uint32_t a;
    asm("{ .reg .u64 t; cvta.to.shared.u64 t, %1; cvt.u32.u64 %0, t; }" : "=r"(a) : "l"(p));
    return a;
}
__device__ __forceinline__ uint32_t lds32(uint32_t a) {
    uint32_t v; asm volatile("ld.shared.b32 %0, [%1];" : "=r"(v) : "r"(a)); return v;
}
__device__ __forceinline__ float ldsf(uint32_t a) {
    float v; asm volatile("ld.shared.f32 %0, [%1];" : "=f"(v) : "r"(a)); return v;
}
__device__ __forceinline__ void sts32(uint32_t a, uint32_t v) {
    asm volatile("st.shared.b32 [%0], %1;" :: "r"(a), "r"(v) : "memory");
}
__device__ __forceinline__ void stsf(uint32_t a, float v) {
    asm volatile("st.shared.f32 [%0], %1;" :: "r"(a), "f"(v) : "memory");
}
__device__ __forceinline__ void cp16(uint32_t dst, const void* src) {
    asm volatile("cp.async.cg.shared.global [%0], [%1], 16;" :: "r"(dst), "l"(src) : "memory");
}
#define CP_COMMIT() asm volatile("cp.async.commit_group;" ::: "memory")

#define LDSM_X4(r, addr) \
    asm volatile("ldmatrix.sync.aligned.m8n8.x4.shared.b16 {%0,%1,%2,%3}, [%4];" \
        : "=r"((r)[0]), "=r"((r)[1]), "=r"((r)[2]), "=r"((r)[3]) : "r"(addr))

#define MMAF16(d, a, b0, b1) \
    asm volatile("mma.sync.aligned.m16n8k16.row.col.f32.f16.f16.f32 " \
        "{%0,%1,%2,%3}, {%4,%5,%6,%7}, {%8,%9}, {%0,%1,%2,%3};" \
        : "+f"((d)[0]), "+f"((d)[1]), "+f"((d)[2]), "+f"((d)[3]) \
        : "r"((a)[0]), "r"((a)[1]), "r"((a)[2]), "r"((a)[3]), "r"(b0), "r"(b1))

__device__ __forceinline__ uint32_t packh2(float lo, float hi) {
    uint32_t r; asm("cvt.rn.f16x2.f32 %0, %1, %2;" : "=r"(r) : "f"(hi), "f"(lo)); return r;
}

// ---------------- prep kernels ----------------------------------------------
__global__ void prep_weights(const float* __restrict__ W_in,
                             const float* __restrict__ W1,
                             const float* __restrict__ W2)
{
    int t = blockIdx.x * blockDim.x + threadIdx.x;
    if (t >= NSUB * 256 * 16) return;
    int kq = t & 15;
    int n  = (t >> 4) & 255;
    int c  = (t >> 12) & 7;
    int l  = t >> 15;
    const float* W = (l == 0) ? W_in : ((l == 1) ? W1 : W2);
    int k = c * 32 + kq * 2;
    unsigned char* base = g_wpack + (size_t)(l * 8 + c) * SUBCH;
    *(uint32_t*)(base + n * SW + kq * 4) = packh2(W[k * 256 + n], W[(k + 1) * 256 + n]);
}

__global__ void prep_latents(const float* __restrict__ lat, int nrows)
{
    long t = (long)blockIdx.x * blockDim.x + threadIdx.x;
    if (t >= (long)nrows * 64) return;
    long r = t >> 6;
    int  q = (int)(t & 63);
    float4 v = ((const float4*)lat)[t];
    *(uint2*)(g_latpack + r * 512 + q * 8) =
        make_uint2(packh2(v.x, v.y), packh2(v.z, v.w));
}

// ---------------- device subroutines ----------------------------------------
// A swizzle: byte address = OFF_AH + m*512 + (off ^ ((m&7)<<4))
__device__ __forceinline__ void gather_tile(uint32_t sb, int tid, int t, int E,
                                            const int* __restrict__ col)
{
    int gm = tid >> 1, gh = tid & 1;     // 2 threads per edge, 256B each
    int e  = t * TILE_M + gm;
    int ee = (e < E) ? e : (E - 1);
    int ci = col[ee];
    const unsigned char* srow = g_latpack + (size_t)ci * 512 + gh * 256;
    uint32_t dA = sb + OFF_AH + gm * 512;
    uint32_t swg = (uint32_t)(gm & 7) << 4;
    #pragma unroll
    for (int j = 0; j < 16; j++)
        cp16(dA + (((uint32_t)(gh * 256 + j * 16)) ^ swg), srow + j * 16);
    CP_COMMIT();
}

__device__ __forceinline__ void pos_tile(uint32_t sb, int tid, int t, int E,
                                         const int* __restrict__ row,
                                         const int* __restrict__ col,
                                         const float* __restrict__ pt,
                                         const float* __restrict__ ps)
{
    if (tid < TILE_M) {
        int e  = t * TILE_M + tid;
        int ee = (e < E) ? e : (E - 1);
        int r  = row[ee], ci = col[ee];
        #pragma unroll
        for (int d = 0; d < 3; d++)
            stsf(sb + OFF_POS + (d * 128 + tid) * 4, pt[r * 3 + d] - ps[ci * 3 + d]);
    }
}

__device__ __forceinline__ void epilogue01(uint32_t sb, int l, int lane,
                                           int m_base, int n_base,
                                           float acc[4][8][4])
{
    const uint32_t swe = (uint32_t)(lane >> 2) << 4;   // (m_lo&7)<<4 == (lane>>2)<<4
    float qv[3][4][2];
    if (l == 0) {
        #pragma unroll
        for (int mt = 0; mt < 4; mt++) {
            int m_lo = m_base + mt * 16 + (lane >> 2);
            #pragma unroll
            for (int d = 0; d < 3; d++) {
                qv[d][mt][0] = ldsf(sb + OFF_POS + (d * 128 + m_lo) * 4);
                qv[d][mt][1] = ldsf(sb + OFF_POS + (d * 128 + m_lo + 8) * 4);
            }
        }
    }
    #pragma unroll
    for (int nt = 0; nt < 8; nt++) {
        const int n0 = n_base + nt * 8 + (lane & 3) * 2;
        const uint32_t cofs = ((uint32_t)(n0 * 2)) ^ swe;
        float bi0 = ldsf(sb + OFF_BIAS + (l * 256 + n0) * 4);
        float bi1 = ldsf(sb + OFF_BIAS + (l * 256 + n0 + 1) * 4);
        float wa0 = 0.f, wa1 = 0.f, wb0 = 0.f, wb1 = 0.f, wc0 = 0.f, wc1 = 0.f;
        if (l == 0) {
            wa0 = ldsf(sb + OFF_WP + n0 * 4);           wa1 = ldsf(sb + OFF_WP + (n0 + 1) * 4);
            wb0 = ldsf(sb + OFF_WP + (256 + n0) * 4);   wb1 = ldsf(sb + OFF_WP + (256 + n0 + 1) * 4);
            wc0 = ldsf(sb + OFF_WP + (512 + n0) * 4);   wc1 = ldsf(sb + OFF_WP + (512 + n0 + 1) * 4);
        }
        #pragma unroll
        for (int mt = 0; mt < 4; mt++) {
            const int m_lo = m_base + mt * 16 + (lane >> 2);
            float x00 = acc[mt][nt][0] + bi0, x01 = acc[mt][nt][1] + bi1;
            float x10 = acc[mt][nt][2] + bi0, x11 = acc[mt][nt][3] + bi1;
            if (l == 0) {
                x00 += qv[0][mt][0] * wa0 + qv[1][mt][0] * wb0 + qv[2][mt][0] * wc0;
                x01 += qv[0][mt][0] * wa1 + qv[1][mt][0] * wb1 + qv[2][mt][0] * wc1;
                x10 += qv[0][mt][1] * wa0 + qv[1][mt][1] * wb0 + qv[2][mt][1] * wc0;
                x11 += qv[0][mt][1] * wa1 + qv[1][mt][1] * wb1 + qv[2][mt][1] * wc1;
            }
            x00 = fmaxf(x00, 0.f); x01 = fmaxf(x01, 0.f);
            x10 = fmaxf(x10, 0.f); x11 = fmaxf(x11, 0.f);
            sts32(sb + OFF_AH + m_lo * 512 + cofs, packh2(x00, x01));
            sts32(sb + OFF_AH + (m_lo + 8) * 512 + cofs, packh2(x10, x11));
            acc[mt][nt][0] = 0.f; acc[mt][nt][1] = 0.f;
            acc[mt][nt][2] = 0.f; acc[mt][nt][3] = 0.f;
        }
    }
}

// ---------------- main persistent kernel ------------------------------------
__global__ void __launch_bounds__(THREADS, 1)
interpnet_mma(const float* __restrict__ pos_source,
              const float* __restrict__ pos_target,
              const int*   __restrict__ row,
              const int*   __restrict__ col,
              const float* __restrict__ W_in, const float* __restrict__ b_in,
              const float* __restrict__ b1,  const float* __restrict__ b2,
              const float* __restrict__ W_out, const float* __restrict__ b_out,
              float* __restrict__ out, int E, int ntiles)
{
    extern __shared__ unsigned char sm[];
    const uint32_t sb = smem_u32(sm);

    const int tid  = threadIdx.x;
    const int lane = tid & 31;
    const int wid  = tid >> 5;
    const int m_base = (wid >> 2) * 64;
    const int n_base = (wid & 3) * 64;

    // ---- one-time consts ----
    for (int i = tid; i < 768; i += THREADS) {
        int l = i >> 8, n = i & 255;
        float v = (l == 0) ? b_in[n] : ((l == 1) ? b1[n] : b2[n]);
        stsf(sb + OFF_BIAS + i * 4, v);
    }
    for (int i = tid; i < 768; i += THREADS) {
        int d = i >> 8, n = i & 255;
        stsf(sb + OFF_WP + i * 4, W_in[(256 + d) * 256 + n]);
    }
    if (tid < 256) stsf(sb + OFF_WOUT + tid * 4, W_out[tid * 2]);

    const int t0 = blockIdx.x;
    if (t0 < ntiles) {
        // stage 0 into ring slot 0 (18 x cp16 per thread)
        const unsigned char* src = g_wpack + tid * 16;
        uint32_t dst = sb + OFF_W + tid * 16;
        #pragma unroll
        for (int i = 0; i < 18; i++) cp16(dst + i * 4096, src + i * 4096);
        CP_COMMIT();
        gather_tile(sb, tid, t0, E, col);
        pos_tile(sb, tid, t0, E, row, col, pos_target, pos_source);
    }

    // A ldmatrix addressing: row base per lane + swizzle constants
    const uint32_t aRow  = sb + OFF_AH + (m_base + (lane & 15)) * 512;
    const uint32_t asw   = (uint32_t)(lane & 7) << 4;
    const uint32_t ahalf = ((uint32_t)(lane >> 4)) << 4;
    // B base: n-row = n_base + lane/4, k-word = lane&3
    const uint32_t bB = sb + OFF_W + (n_base + (lane >> 2)) * SW + (lane & 3) * 4;

    #pragma unroll 1
    for (int t = t0; t < ntiles; t += gridDim.x) {
        const bool last = (t + (int)gridDim.x >= ntiles);

        float acc[4][8][4];
        #pragma unroll
        for (int mt = 0; mt < 4; mt++)
            #pragma unroll
            for (int nt = 0; nt < 8; nt++)
                #pragma unroll
                for (int q = 0; q < 4; q++) acc[mt][nt][q] = 0.f;

        #pragma unroll 1
        for (int s = 0; s < NST; s++) {
            const int l = s >> 1;                      // layer
            const int sl = s & 1;                      // stage within layer
            const int slot = s & 1;                    // ring-2 slot
            const uint32_t kbase = (uint32_t)(sl * 256); // A byte offset of stage

            uint32_t ahA[4][4], ahB[4][4];
            if (sl) {   // A stable within layer: hoist subgroup pair 0
                #pragma unroll
                for (int mt = 0; mt < 4; mt++) {
                    LDSM_X4(ahA[mt], aRow + mt * 8192 + ((kbase + ahalf) ^ asw));
                    LDSM_X4(ahB[mt], aRow + mt * 8192 + ((kbase + 32 + ahalf) ^ asw));
                }
            }
            asm volatile("cp.async.wait_group 0;" ::: "memory");
            __syncthreads();

            // prefetch stage s+1 into the other ring slot
            {
                int cn = s + 1;
                bool issue = true;
                if (cn >= NST) { cn -= NST; issue = !last; }
                if (issue) {
                    const unsigned char* csrc = g_wpack + (size_t)cn * STB + tid * 16;
                    uint32_t cdst = sb + OFF_W + ((cn & 1) * STB) + tid * 16;
                    #pragma unroll
                    for (int i = 0; i < 18; i++) cp16(cdst + i * 4096, csrc + i * 4096);
                    CP_COMMIT();
                }
            }

            if (!sl) {
                #pragma unroll
                for (int mt = 0; mt < 4; mt++) {
                    LDSM_X4(ahA[mt], aRow + mt * 8192 + ((kbase + ahalf) ^ asw));
                    LDSM_X4(ahB[mt], aRow + mt * 8192 + ((kbase + 32 + ahalf) ^ asw));
                }
            }

            const uint32_t wb = bB + slot * STB;
            // 4 subgroup pairs; pair p = slab p (bytes p*SUBCH), halves +0/+32
            #pragma unroll
            for (int p = 0; p < 4; p++) {
                if (p) {
                    #pragma unroll
                    for (int mt = 0; mt < 4; mt++) {
                        LDSM_X4(ahA[mt], aRow + mt * 8192 + ((kbase + p * 64 + ahalf) ^ asw));
                        LDSM_X4(ahB[mt], aRow + mt * 8192 + ((kbase + p * 64 + 32 + ahalf) ^ asw));
                    }
                }
                #pragma unroll
                for (int nt = 0; nt < 8; nt++) {
                    uint32_t o = wb + p * SUBCH + nt * 8 * SW;
                    uint32_t b0 = lds32(o), b1 = lds32(o + 16);
                    #pragma unroll
                    for (int mt = 0; mt < 4; mt++)
                        MMAF16(acc[mt][nt], ahA[mt], b0, b1);
                }
                #pragma unroll
                for (int nt = 0; nt < 8; nt++) {
                    uint32_t o = wb + p * SUBCH + nt * 8 * SW + 32;
                    uint32_t b0 = lds32(o), b1 = lds32(o + 16);
                    #pragma unroll
                    for (int mt = 0; mt < 4; mt++)
                        MMAF16(acc[mt][nt], ahB[mt], b0, b1);
                }
            }

            if (sl == 1) {
                __syncthreads();                       // all A reads of layer done
                if (l < 2) epilogue01(sb, l, lane, m_base, n_base, acc);
            }
        }

        // ---- tile boundary: next-tile gather overlaps final epilogue ----
        const int t2 = t + (int)gridDim.x;
        if (t2 < ntiles) {
            gather_tile(sb, tid, t2, E, col);
            pos_tile(sb, tid, t2, E, row, col, pos_target, pos_source);
        }

        // layer-2 epilogue: project to W_out[:,0]
        float sfin[4][2] = {{0.f,0.f},{0.f,0.f},{0.f,0.f},{0.f,0.f}};
        #pragma unroll
        for (int nt = 0; nt < 8; nt++) {
            const int n0 = n_base + nt * 8 + (lane & 3) * 2;
            float wo0 = ldsf(sb + OFF_WOUT + n0 * 4);
            float wo1 = ldsf(sb + OFF_WOUT + (n0 + 1) * 4);
            float bi0 = ldsf(sb + OFF_BIAS + (512 + n0) * 4);
            float bi1 = ldsf(sb + OFF_BIAS + (512 + n0 + 1) * 4);
            #pragma unroll
            for (int mt = 0; mt < 4; mt++) {
                sfin[mt][0] += (acc[mt][nt][0] + bi0) * wo0 + (acc[mt][nt][1] + bi1) * wo1;
                sfin[mt][1] += (acc[mt][nt][2] + bi0) * wo0 + (acc[mt][nt][3] + bi1) * wo1;
            }
        }
        #pragma unroll
        for (int mt = 0; mt < 4; mt++) {
            float s0 = sfin[mt][0], s1 = sfin[mt][1];
            s0 += __shfl_xor_sync(0xffffffffu, s0, 1);
            s0 += __shfl_xor_sync(0xffffffffu, s0, 2);
            s1 += __shfl_xor_sync(0xffffffffu, s1, 1);
            s1 += __shfl_xor_sync(0xffffffffu, s1, 2);
            if ((lane & 3) == 0) {
                int m_lo = m_base + mt * 16 + (lane >> 2);
                stsf(sb + OFF_RED + (m_lo * 4 + (wid & 3)) * 4, s0);
                stsf(sb + OFF_RED + ((m_lo + 8) * 4 + (wid & 3)) * 4, s1);
            }
        }
        __syncthreads();
        if (tid < TILE_M) {
            float s = ldsf(sb + OFF_RED + (tid * 4 + 0) * 4)
                    + ldsf(sb + OFF_RED + (tid * 4 + 1) * 4)
                    + ldsf(sb + OFF_RED + (tid * 4 + 2) * 4)
                    + ldsf(sb + OFF_RED + (tid * 4 + 3) * 4);
            int e = t * TILE_M + tid;
            if (e < E) out[e] = s + __ldg(b_out);
        }
    }
}

// ---------------- launch -----------------------------------------------------
extern "C" void kernel_launch(void* const* d_in, const int* in_sizes, int n_in,
                              void* d_out, int out_size)
{
    const float* pos_source = (const float*)d_in[0];
    const float* pos_target = (const float*)d_in[1];
    const float* latents    = (const float*)d_in[2];
    const int*   row        = (const int*)  d_in[3];
    const int*   col        = (const int*)  d_in[4];
    const float* W_in  = (const float*)d_in[5];
    const float* b_in  = (const float*)d_in[6];
    const float* W1    = (const float*)d_in[7];
    const float* b1    = (const float*)d_in[8];
    const float* W2    = (const float*)d_in[9];
    const float* b2    = (const float*)d_in[10];
    const float* W_out = (const float*)d_in[11];
    const float* b_out = (const float*)d_in[12];
    float* out = (float*)d_out;

    const int E = in_sizes[3];
    int nrows = in_sizes[2] / 256;
    if (nrows > NSRC_MAX) nrows = NSRC_MAX;

    prep_weights<<<(NSUB * 256 * 16 + 255) / 256, 256>>>(W_in, W1, W2);
    prep_latents<<<(int)(((long)nrows * 64 + 255) / 256), 256>>>(latents, nrows);

    int numSMs = 148;
    cudaDeviceGetAttribute(&numSMs, cudaDevAttrMultiProcessorCount, 0);

    const int ntiles = (E + TILE_M - 1) / TILE_M;
    int grid = numSMs < ntiles ? numSMs : ntiles;

    cudaFuncSetAttribute(interpnet_mma,
                         cudaFuncAttributeMaxDynamicSharedMemorySize, SMEM_TOTAL);
    interpnet_mma<<<grid, THREADS, SMEM_TOTAL>>>(
        pos_source, pos_target, row, col,
        W_in, b_in, b1, b2, W_out, b_out, out, E, ntiles);
}

// round 16
// speedup vs baseline: 1.8744x; 1.8744x over previous
#include <cuda_runtime.h>
#include <cuda_fp16.h>
#include <cstdint>

// ============================================================================
// InterpNet via mma.sync HMMA, single fp16 term, fp32 accumulate.
// Round 16: R12 structure (proven 650us) + layer-2 GEMM folded into a
// precomputed vector w2v = W2 @ W_out[:,0]  (out = relu(x2)@w2v + bconst).
// 8 stages/tile (2 layers), ring-3 + wait_group 1, persistent CTAs.
// ============================================================================

#define THREADS 256
#define TILE_M  128
#define SUBCH   20480        // prep sub-chunk (k=32 slab), SW=80
#define STB     40960        // stage bytes (k=64)
#define NST     8            // stages per tile (4 per layer, 2 layers)
#define SW      80           // W smem row stride (conflict-free)
#define SA      528          // A smem row stride (512B fp16 + 16B pad)
#define NSUB    16           // k=32 slabs in g_wpack (W_in, W1)
#define NSRC_MAX 100000

// smem offsets
#define OFF_AH    0           // fp16 A [128][264]                   67584
#define OFF_W     67584       // W ring 3 x 40960                   122880
#define OFF_BIAS  190464      // f32[2][256]  (b_in, b1)
#define OFF_WP    192512      // f32[3][256]  (W_in rows 256..258)
#define OFF_W2V   195584      // f32[256]     (W2 @ wout)
#define OFF_POS   196608      // f32[3][128]
#define OFF_RED   198144      // f32[128][4]
#define SMEM_TOTAL 200192

__device__ __align__(16) unsigned char g_wpack[NSUB * SUBCH];             // 320 KB
__device__ __align__(16) unsigned char g_latpack[(size_t)NSRC_MAX * 512]; // 51.2 MB
__device__ float g_w2v[256];
__device__ float g_bconst;

// ---------------- helpers ---------------------------------------------------
__device__ __forceinline__ uint32_t smem_u32(const void* p) {
    uint32_t a;
    asm("{ .reg .u64 t; cvta.to.shared.u64 t, %1; cvt.u32.u64 %0, t; }" : "=r"(a) : "l"(p));
    return a;
}
__device__ __forceinline__ uint32_t lds32(uint32_t a) {
    uint32_t v; asm volatile("ld.shared.b32 %0, [%1];" : "=r"(v) : "r"(a)); return v;
}
__device__ __forceinline__ float ldsf(uint32_t a) {
    float v; asm volatile("ld.shared.f32 %0, [%1];" : "=f"(v) : "r"(a)); return v;
}
__device__ __forceinline__ void sts32(uint32_t a, uint32_t v) {
    asm volatile("st.shared.b32 [%0], %1;" :: "r"(a), "r"(v) : "memory");
}
__device__ __forceinline__ void stsf(uint32_t a, float v) {
    asm volatile("st.shared.f32 [%0], %1;" :: "r"(a), "f"(v) : "memory");
}
__device__ __forceinline__ void cp16(uint32_t dst, const void* src) {
    asm volatile("cp.async.cg.shared.global [%0], [%1], 16;" :: "r"(dst), "l"(src) : "memory");
}
#define CP_COMMIT() asm volatile("cp.async.commit_group;" ::: "memory")

#define LDSM_X4(r, addr) \
    asm volatile("ldmatrix.sync.aligned.m8n8.x4.shared.b16 {%0,%1,%2,%3}, [%4];" \
        : "=r"((r)[0]), "=r"((r)[1]), "=r"((r)[2]), "=r"((r)[3]) : "r"(addr))

#define MMAF16(d, a, b0, b1) \
    asm volatile("mma.sync.aligned.m16n8k16.row.col.f32.f16.f16.f32 " \
        "{%0,%1,%2,%3}, {%4,%5,%6,%7}, {%8,%9}, {%0,%1,%2,%3};" \
        : "+f"((d)[0]), "+f"((d)[1]), "+f"((d)[2]), "+f"((d)[3]) \
        : "r"((a)[0]), "r"((a)[1]), "r"((a)[2]), "r"((a)[3]), "r"(b0), "r"(b1))

__device__ __forceinline__ uint32_t packh2(float lo, float hi) {
    uint32_t r; asm("cvt.rn.f16x2.f32 %0, %1, %2;" : "=r"(r) : "f"(hi), "f"(lo)); return r;
}

// ---------------- prep kernels ----------------------------------------------
__global__ void prep_weights(const float* __restrict__ W_in,
                             const float* __restrict__ W1)
{
    int t = blockIdx.x * blockDim.x + threadIdx.x;
    if (t >= NSUB * 256 * 16) return;
    int kq = t & 15;
    int n  = (t >> 4) & 255;
    int c  = (t >> 12) & 7;
    int l  = t >> 15;
    const float* W = (l == 0) ? W_in : W1;
    int k = c * 32 + kq * 2;
    unsigned char* base = g_wpack + (size_t)(l * 8 + c) * SUBCH;
    *(uint32_t*)(base + n * SW + kq * 4) = packh2(W[k * 256 + n], W[(k + 1) * 256 + n]);
}

__global__ void prep_w2v(const float* __restrict__ W2,
                         const float* __restrict__ b2,
                         const float* __restrict__ W_out,
                         const float* __restrict__ b_out)
{
    int n = threadIdx.x;
    float s = 0.f;
    for (int j = 0; j < 256; j++) s += W2[n * 256 + j] * W_out[j * 2];
    g_w2v[n] = s;
    if (n == 0) {
        float b = 0.f;
        for (int j = 0; j < 256; j++) b += b2[j] * W_out[j * 2];
        g_bconst = b + b_out[0];
    }
}

__global__ void prep_latents(const float* __restrict__ lat, int nrows)
{
    long t = (long)blockIdx.x * blockDim.x + threadIdx.x;
    if (t >= (long)nrows * 64) return;
    long r = t >> 6;
    int  q = (int)(t & 63);
    float4 v = ((const float4*)lat)[t];
    *(uint2*)(g_latpack + r * 512 + q * 8) =
        make_uint2(packh2(v.x, v.y), packh2(v.z, v.w));
}

// ---------------- device subroutines ----------------------------------------
__device__ __forceinline__ void gather_tile(uint32_t sb, int tid, int t, int E,
                                            const int* __restrict__ col)
{
    int gm = tid >> 1, gh = tid & 1;
    int e  = t * TILE_M + gm;
    int ee = (e < E) ? e : (E - 1);
    int ci = col[ee];
    const unsigned char* srow = g_latpack + (size_t)ci * 512 + gh * 256;
    uint32_t dA = sb + OFF_AH + gm * SA + gh * 256;
    #pragma unroll
    for (int j = 0; j < 16; j++) cp16(dA + j * 16, srow + j * 16);
    CP_COMMIT();
}

__device__ __forceinline__ void pos_tile(uint32_t sb, int tid, int t, int E,
                                         const int* __restrict__ row,
                                         const int* __restrict__ col,
                                         const float* __restrict__ pt,
                                         const float* __restrict__ ps)
{
    if (tid < TILE_M) {
        int e  = t * TILE_M + tid;
        int ee = (e < E) ? e : (E - 1);
        int r  = row[ee], ci = col[ee];
        #pragma unroll
        for (int d = 0; d < 3; d++)
            stsf(sb + OFF_POS + (d * 128 + tid) * 4, pt[r * 3 + d] - ps[ci * 3 + d]);
    }
}

// layer-0 epilogue: +b_in +pos_rel rows, relu, pack fp16 back into A
__device__ __forceinline__ void epilogue0(uint32_t sb, int lane,
                                          int m_base, int n_base,
                                          float acc[4][8][4])
{
    float qv[3][4][2];
    #pragma unroll
    for (int mt = 0; mt < 4; mt++) {
        int m_lo = m_base + mt * 16 + (lane >> 2);
        #pragma unroll
        for (int d = 0; d < 3; d++) {
            qv[d][mt][0] = ldsf(sb + OFF_POS + (d * 128 + m_lo) * 4);
            qv[d][mt][1] = ldsf(sb + OFF_POS + (d * 128 + m_lo + 8) * 4);
        }
    }
    #pragma unroll
    for (int nt = 0; nt < 8; nt++) {
        const int n0 = n_base + nt * 8 + (lane & 3) * 2;
        float bi0 = ldsf(sb + OFF_BIAS + n0 * 4);
        float bi1 = ldsf(sb + OFF_BIAS + (n0 + 1) * 4);
        float wa0 = ldsf(sb + OFF_WP + n0 * 4);          float wa1 = ldsf(sb + OFF_WP + (n0 + 1) * 4);
        float wb0 = ldsf(sb + OFF_WP + (256 + n0) * 4);  float wb1 = ldsf(sb + OFF_WP + (256 + n0 + 1) * 4);
        float wc0 = ldsf(sb + OFF_WP + (512 + n0) * 4);  float wc1 = ldsf(sb + OFF_WP + (512 + n0 + 1) * 4);
        #pragma unroll
        for (int mt = 0; mt < 4; mt++) {
            const int m_lo = m_base + mt * 16 + (lane >> 2);
            float x00 = acc[mt][nt][0] + bi0, x01 = acc[mt][nt][1] + bi1;
            float x10 = acc[mt][nt][2] + bi0, x11 = acc[mt][nt][3] + bi1;
            x00 += qv[0][mt][0] * wa0 + qv[1][mt][0] * wb0 + qv[2][mt][0] * wc0;
            x01 += qv[0][mt][0] * wa1 + qv[1][mt][0] * wb1 + qv[2][mt][0] * wc1;
            x10 += qv[0][mt][1] * wa0 + qv[1][mt][1] * wb0 + qv[2][mt][1] * wc0;
            x11 += qv[0][mt][1] * wa1 + qv[1][mt][1] * wb1 + qv[2][mt][1] * wc1;
            x00 = fmaxf(x00, 0.f); x01 = fmaxf(x01, 0.f);
            x10 = fmaxf(x10, 0.f); x11 = fmaxf(x11, 0.f);
            sts32(sb + OFF_AH + m_lo * SA + n0 * 2, packh2(x00, x01));
            sts32(sb + OFF_AH + (m_lo + 8) * SA + n0 * 2, packh2(x10, x11));
            acc[mt][nt][0] = 0.f; acc[mt][nt][1] = 0.f;
            acc[mt][nt][2] = 0.f; acc[mt][nt][3] = 0.f;
        }
    }
}

// ---------------- main persistent kernel ------------------------------------
__global__ void __launch_bounds__(THREADS, 1)
interpnet_mma(const float* __restrict__ pos_source,
              const float* __restrict__ pos_target,
              const int*   __restrict__ row,
              const int*   __restrict__ col,
              const float* __restrict__ W_in, const float* __restrict__ b_in,
              const float* __restrict__ b1,
              float* __restrict__ out, int E, int ntiles)
{
    extern __shared__ unsigned char sm[];
    const uint32_t sb = smem_u32(sm);

    const int tid  = threadIdx.x;
    const int lane = tid & 31;
    const int wid  = tid >> 5;
    const int m_base = (wid >> 2) * 64;
    const int n_base = (wid & 3) * 64;

    // ---- one-time consts ----
    for (int i = tid; i < 512; i += THREADS) {
        int l = i >> 8, n = i & 255;
        stsf(sb + OFF_BIAS + i * 4, (l == 0) ? b_in[n] : b1[n]);
    }
    for (int i = tid; i < 768; i += THREADS) {
        int d = i >> 8, n = i & 255;
        stsf(sb + OFF_WP + i * 4, W_in[(256 + d) * 256 + n]);
    }
    if (tid < 256) stsf(sb + OFF_W2V + tid * 4, g_w2v[tid]);

    const int t0 = blockIdx.x;
    if (t0 < ntiles) {
        // stages 0,1 into ring slots 0,1
        #pragma unroll
        for (int cc = 0; cc < 2; cc++) {
            const unsigned char* src = g_wpack + (size_t)cc * STB + tid * 16;
            uint32_t dst = sb + OFF_W + cc * STB + tid * 16;
            #pragma unroll
            for (int i = 0; i < 10; i++) cp16(dst + i * 4096, src + i * 4096);
            CP_COMMIT();
        }
        gather_tile(sb, tid, t0, E, col);
        pos_tile(sb, tid, t0, E, row, col, pos_target, pos_source);
    }

    const uint32_t aH = sb + OFF_AH + (m_base + (lane & 15)) * SA + ((lane >> 4) << 4);
    const uint32_t bB = sb + OFF_W + (n_base + (lane >> 2)) * SW + (lane & 3) * 4;
    const float bconst = g_bconst;

    int slot = 0;   // continuous ring-3 slot counter (NST=8 not divisible by 3)

    #pragma unroll 1
    for (int t = t0; t < ntiles; t += gridDim.x) {
        const bool last = (t + (int)gridDim.x >= ntiles);

        float acc[4][8][4];
        #pragma unroll
        for (int mt = 0; mt < 4; mt++)
            #pragma unroll
            for (int nt = 0; nt < 8; nt++)
                #pragma unroll
                for (int q = 0; q < 4; q++) acc[mt][nt][q] = 0.f;

        #pragma unroll 1
        for (int s = 0; s < NST; s++) {
            const int l = s >> 2;                     // layer (0 or 1)
            const int sl = s & 3;                     // stage within layer
            const uint32_t ka = (uint32_t)(sl * 128); // A byte offset

            uint32_t ah0[4][4], ah1[4][4];
            if (sl) {   // A stable within layer: hoist first two k-subgroups
                #pragma unroll
                for (int mt = 0; mt < 4; mt++) {
                    LDSM_X4(ah0[mt], aH + mt * 16 * SA + ka);
                    LDSM_X4(ah1[mt], aH + mt * 16 * SA + ka + 32);
                }
            }
            if (s == 0) asm volatile("cp.async.wait_group 0;" ::: "memory");
            else        asm volatile("cp.async.wait_group 1;" ::: "memory");
            __syncthreads();

            // prefetch stage s+2 into ring slot (slot+2)%3
            {
                int cn = s + 2;
                bool issue = true;
                if (cn >= NST) { cn -= NST; issue = !last; }
                if (issue) {
                    int ps = slot + 2; if (ps >= 3) ps -= 3;
                    const unsigned char* csrc = g_wpack + (size_t)cn * STB + tid * 16;
                    uint32_t cdst = sb + OFF_W + (uint32_t)ps * STB + tid * 16;
                    #pragma unroll
                    for (int i = 0; i < 10; i++) cp16(cdst + i * 4096, csrc + i * 4096);
                    CP_COMMIT();
                }
            }

            if (!sl) {
                #pragma unroll
                for (int mt = 0; mt < 4; mt++) {
                    LDSM_X4(ah0[mt], aH + mt * 16 * SA + ka);
                    LDSM_X4(ah1[mt], aH + mt * 16 * SA + ka + 32);
                }
            }

            const uint32_t wb = bB + (uint32_t)slot * STB;
            // sub-chunk 0 (k 0..31 of stage)
            #pragma unroll
            for (int nt = 0; nt < 8; nt++) {
                uint32_t o = wb + nt * 8 * SW;
                uint32_t b0 = lds32(o), b1w = lds32(o + 16);
                #pragma unroll
                for (int mt = 0; mt < 4; mt++)
                    MMAF16(acc[mt][nt], ah0[mt], b0, b1w);
            }
            #pragma unroll
            for (int nt = 0; nt < 8; nt++) {
                uint32_t o = wb + nt * 8 * SW + 32;
                uint32_t b0 = lds32(o), b1w = lds32(o + 16);
                #pragma unroll
                for (int mt = 0; mt < 4; mt++)
                    MMAF16(acc[mt][nt], ah1[mt], b0, b1w);
            }
            // sub-chunk 1 (k 32..63 of stage)
            {
                uint32_t ah2[4][4], ah3[4][4];
                #pragma unroll
                for (int mt = 0; mt < 4; mt++) {
                    LDSM_X4(ah2[mt], aH + mt * 16 * SA + ka + 64);
                    LDSM_X4(ah3[mt], aH + mt * 16 * SA + ka + 96);
                }
                #pragma unroll
                for (int nt = 0; nt < 8; nt++) {
                    uint32_t o = wb + SUBCH + nt * 8 * SW;
                    uint32_t b0 = lds32(o), b1w = lds32(o + 16);
                    #pragma unroll
                    for (int mt = 0; mt < 4; mt++)
                        MMAF16(acc[mt][nt], ah2[mt], b0, b1w);
                }
                #pragma unroll
                for (int nt = 0; nt < 8; nt++) {
                    uint32_t o = wb + SUBCH + nt * 8 * SW + 32;
                    uint32_t b0 = lds32(o), b1w = lds32(o + 16);
                    #pragma unroll
                    for (int mt = 0; mt < 4; mt++)
                        MMAF16(acc[mt][nt], ah3[mt], b0, b1w);
                }
            }

            if (++slot >= 3) slot = 0;

            if (sl == 3) {
                __syncthreads();                       // all A reads of layer done
                if (l == 0) epilogue0(sb, lane, m_base, n_base, acc);
            }
        }

        // ---- tile boundary: next-tile gather overlaps final epilogue ----
        const int t2 = t + (int)gridDim.x;
        if (t2 < ntiles) {
            gather_tile(sb, tid, t2, E, col);
            pos_tile(sb, tid, t2, E, row, col, pos_target, pos_source);
        }

        // final epilogue: out = relu(acc + b1) . w2v  (all fp32, register-resident)
        float sfin[4][2] = {{0.f,0.f},{0.f,0.f},{0.f,0.f},{0.f,0.f}};
        #pragma unroll
        for (int nt = 0; nt < 8; nt++) {
            const int n0 = n_base + nt * 8 + (lane & 3) * 2;
            float bi0 = ldsf(sb + OFF_BIAS + (256 + n0) * 4);
            float bi1 = ldsf(sb + OFF_BIAS + (256 + n0 + 1) * 4);
            float w0  = ldsf(sb + OFF_W2V + n0 * 4);
            float w1  = ldsf(sb + OFF_W2V + (n0 + 1) * 4);
            #pragma unroll
            for (int mt = 0; mt < 4; mt++) {
                sfin[mt][0] += fmaxf(acc[mt][nt][0] + bi0, 0.f) * w0
                             + fmaxf(acc[mt][nt][1] + bi1, 0.f) * w1;
                sfin[mt][1] += fmaxf(acc[mt][nt][2] + bi0, 0.f) * w0
                             + fmaxf(acc[mt][nt][3] + bi1, 0.f) * w1;
            }
        }
        #pragma unroll
        for (int mt = 0; mt < 4; mt++) {
            float s0 = sfin[mt][0], s1 = sfin[mt][1];
            s0 += __shfl_xor_sync(0xffffffffu, s0, 1);
            s0 += __shfl_xor_sync(0xffffffffu, s0, 2);
            s1 += __shfl_xor_sync(0xffffffffu, s1, 1);
            s1 += __shfl_xor_sync(0xffffffffu, s1, 2);
            if ((lane & 3) == 0) {
                int m_lo = m_base + mt * 16 + (lane >> 2);
                stsf(sb + OFF_RED + (m_lo * 4 + (wid & 3)) * 4, s0);
                stsf(sb + OFF_RED + ((m_lo + 8) * 4 + (wid & 3)) * 4, s1);
            }
        }
        __syncthreads();
        if (tid < TILE_M) {
            float s = ldsf(sb + OFF_RED + (tid * 4 + 0) * 4)
                    + ldsf(sb + OFF_RED + (tid * 4 + 1) * 4)
                    + ldsf(sb + OFF_RED + (tid * 4 + 2) * 4)
                    + ldsf(sb + OFF_RED + (tid * 4 + 3) * 4);
            int e = t * TILE_M + tid;
            if (e < E) out[e] = s + bconst;
        }
    }
}

// ---------------- launch -----------------------------------------------------
extern "C" void kernel_launch(void* const* d_in, const int* in_sizes, int n_in,
                              void* d_out, int out_size)
{
    const float* pos_source = (const float*)d_in[0];
    const float* pos_target = (const float*)d_in[1];
    const float* latents    = (const float*)d_in[2];
    const int*   row        = (const int*)  d_in[3];
    const int*   col        = (const int*)  d_in[4];
    const float* W_in  = (const float*)d_in[5];
    const float* b_in  = (const float*)d_in[6];
    const float* W1    = (const float*)d_in[7];
    const float* b1    = (const float*)d_in[8];
    const float* W2    = (const float*)d_in[9];
    const float* b2    = (const float*)d_in[10];
    const float* W_out = (const float*)d_in[11];
    const float* b_out = (const float*)d_in[12];
    float* out = (float*)d_out;

    const int E = in_sizes[3];
    int nrows = in_sizes[2] / 256;
    if (nrows > NSRC_MAX) nrows = NSRC_MAX;

    prep_weights<<<(NSUB * 256 * 16 + 255) / 256, 256>>>(W_in, W1);
    prep_w2v<<<1, 256>>>(W2, b2, W_out, b_out);
    prep_latents<<<(int)(((long)nrows * 64 + 255) / 256), 256>>>(latents, nrows);

    int numSMs = 148;
    cudaDeviceGetAttribute(&numSMs, cudaDevAttrMultiProcessorCount, 0);

    const int ntiles = (E + TILE_M - 1) / TILE_M;
    int grid = numSMs < ntiles ? numSMs : ntiles;

    cudaFuncSetAttribute(interpnet_mma,
                         cudaFuncAttributeMaxDynamicSharedMemorySize, SMEM_TOTAL);
    interpnet_mma<<<grid, THREADS, SMEM_TOTAL>>>(
        pos_source, pos_target, row, col,
        W_in, b_in, b1, out, E, ntiles);
}

// round 17
// speedup vs baseline: 1.9721x; 1.0521x over previous
#include <cuda_runtime.h>
#include <cuda_fp16.h>
#include <cstdint>

// ============================================================================
// InterpNet via mma.sync HMMA, single fp16 term, fp32 accumulate.
// Round 17: R16 + (a) interleaved W layout -> lds64 B pairs, (b) register
// double-buffered B pipeline, (c) all-16 LDSM hoist, (d) parallel prep_w2v.
// 8 stages/tile (2 layers; layer2 folded into w2v), ring-3, persistent CTAs.
// ============================================================================

#define THREADS 256
#define TILE_M  128
#define SUBCH   20480        // prep sub-chunk (k=32 slab), SW=80
#define STB     40960        // stage bytes (k=64)
#define NST     8            // stages per tile (4 per layer, 2 layers)
#define SW      80           // W smem row stride (conflict-free)
#define SA      528          // A smem row stride (512B fp16 + 16B pad)
#define NSUB    16           // k=32 slabs in g_wpack (W_in, W1)
#define NSRC_MAX 100000

// smem offsets
#define OFF_AH    0           // fp16 A [128][264]                   67584
#define OFF_W     67584       // W ring 3 x 40960                   122880
#define OFF_BIAS  190464      // f32[2][256]  (b_in, b1)
#define OFF_WP    192512      // f32[3][256]  (W_in rows 256..258)
#define OFF_W2V   195584      // f32[256]     (W2 @ wout)
#define OFF_POS   196608      // f32[3][128]
#define OFF_RED   198144      // f32[128][4]
#define SMEM_TOTAL 200192

__device__ __align__(16) unsigned char g_wpack[NSUB * SUBCH];             // 320 KB
__device__ __align__(16) unsigned char g_latpack[(size_t)NSRC_MAX * 512]; // 51.2 MB
__device__ float g_w2v[256];
__device__ float g_bconst;

// ---------------- helpers ---------------------------------------------------
__device__ __forceinline__ uint32_t smem_u32(const void* p) {
    uint32_t a;
    asm("{ .reg .u64 t; cvta.to.shared.u64 t, %1; cvt.u32.u64 %0, t; }" : "=r"(a) : "l"(p));
    return a;
}
__device__ __forceinline__ void lds64(uint32_t& v0, uint32_t& v1, uint32_t a) {
    asm volatile("ld.shared.v2.b32 {%0,%1}, [%2];" : "=r"(v0), "=r"(v1) : "r"(a));
}
__device__ __forceinline__ float ldsf(uint32_t a) {
    float v; asm volatile("ld.shared.f32 %0, [%1];" : "=f"(v) : "r"(a)); return v;
}
__device__ __forceinline__ void sts32(uint32_t a, uint32_t v) {
    asm volatile("st.shared.b32 [%0], %1;" :: "r"(a), "r"(v) : "memory");
}
__device__ __forceinline__ void stsf(uint32_t a, float v) {
    asm volatile("st.shared.f32 [%0], %1;" :: "r"(a), "f"(v) : "memory");
}
__device__ __forceinline__ void cp16(uint32_t dst, const void* src) {
    asm volatile("cp.async.cg.shared.global [%0], [%1], 16;" :: "r"(dst), "l"(src) : "memory");
}
#define CP_COMMIT() asm volatile("cp.async.commit_group;" ::: "memory")

#define LDSM_X4(r, addr) \
    asm volatile("ldmatrix.sync.aligned.m8n8.x4.shared.b16 {%0,%1,%2,%3}, [%4];" \
        : "=r"((r)[0]), "=r"((r)[1]), "=r"((r)[2]), "=r"((r)[3]) : "r"(addr))

#define MMAF16(d, a, b0, b1) \
    asm volatile("mma.sync.aligned.m16n8k16.row.col.f32.f16.f16.f32 " \
        "{%0,%1,%2,%3}, {%4,%5,%6,%7}, {%8,%9}, {%0,%1,%2,%3};" \
        : "+f"((d)[0]), "+f"((d)[1]), "+f"((d)[2]), "+f"((d)[3]) \
        : "r"((a)[0]), "r"((a)[1]), "r"((a)[2]), "r"((a)[3]), "r"(b0), "r"(b1))

__device__ __forceinline__ uint32_t packh2(float lo, float hi) {
    uint32_t r; asm("cvt.rn.f16x2.f32 %0, %1, %2;" : "=r"(r) : "f"(hi), "f"(lo)); return r;
}

// ---------------- prep kernels ----------------------------------------------
// W layout per row (64B = 16 words, two 32B k16-groups). Within each group the
// 8 words are interleaved [w0 w4 w1 w5 w2 w6 w3 w7] so thread j=lane&3 reads
// its (b0,b1)=(w_j, w_{j+4}) with ONE lds64 at byte j*8.
__global__ void prep_weights(const float* __restrict__ W_in,
                             const float* __restrict__ W1)
{
    int t = blockIdx.x * blockDim.x + threadIdx.x;
    if (t >= NSUB * 256 * 16) return;
    int kq = t & 15;
    int n  = (t >> 4) & 255;
    int c  = (t >> 12) & 7;
    int l  = t >> 15;
    const float* W = (l == 0) ? W_in : W1;
    int k = c * 32 + kq * 2;
    int g = kq >> 3, j = kq & 7;
    int pos = g * 32 + ((j < 4) ? 8 * j : 8 * (j - 4) + 4);
    unsigned char* base = g_wpack + (size_t)(l * 8 + c) * SUBCH;
    *(uint32_t*)(base + n * SW + pos) = packh2(W[k * 256 + n], W[(k + 1) * 256 + n]);
}

// parallel w2v: 257 blocks x 64 threads; block n<256 -> g_w2v[n], n==256 -> bconst
__global__ void prep_w2v(const float* __restrict__ W2,
                         const float* __restrict__ b2,
                         const float* __restrict__ W_out,
                         const float* __restrict__ b_out)
{
    __shared__ float red[2];
    int n = blockIdx.x, tid = threadIdx.x;
    float s = 0.f;
    if (n < 256) {
        for (int j = tid; j < 256; j += 64) s += W2[n * 256 + j] * W_out[j * 2];
    } else {
        for (int j = tid; j < 256; j += 64) s += b2[j] * W_out[j * 2];
    }
    #pragma unroll
    for (int off = 16; off; off >>= 1) s += __shfl_xor_sync(0xffffffffu, s, off);
    if ((tid & 31) == 0) red[tid >> 5] = s;
    __syncthreads();
    if (tid == 0) {
        float v = red[0] + red[1];
        if (n < 256) g_w2v[n] = v;
        else         g_bconst = v + b_out[0];
    }
}

__global__ void prep_latents(const float* __restrict__ lat, int nrows)
{
    long t = (long)blockIdx.x * blockDim.x + threadIdx.x;
    if (t >= (long)nrows * 64) return;
    long r = t >> 6;
    int  q = (int)(t & 63);
    float4 v = ((const float4*)lat)[t];
    *(uint2*)(g_latpack + r * 512 + q * 8) =
        make_uint2(packh2(v.x, v.y), packh2(v.z, v.w));
}

// ---------------- device subroutines ----------------------------------------
__device__ __forceinline__ void gather_tile(uint32_t sb, int tid, int t, int E,
                                            const int* __restrict__ col)
{
    int gm = tid >> 1, gh = tid & 1;
    int e  = t * TILE_M + gm;
    int ee = (e < E) ? e : (E - 1);
    int ci = col[ee];
    const unsigned char* srow = g_latpack + (size_t)ci * 512 + gh * 256;
    uint32_t dA = sb + OFF_AH + gm * SA + gh * 256;
    #pragma unroll
    for (int j = 0; j < 16; j++) cp16(dA + j * 16, srow + j * 16);
    CP_COMMIT();
}

__device__ __forceinline__ void pos_tile(uint32_t sb, int tid, int t, int E,
                                         const int* __restrict__ row,
                                         const int* __restrict__ col,
                                         const float* __restrict__ pt,
                                         const float* __restrict__ ps)
{
    if (tid < TILE_M) {
        int e  = t * TILE_M + tid;
        int ee = (e < E) ? e : (E - 1);
        int r  = row[ee], ci = col[ee];
        #pragma unroll
        for (int d = 0; d < 3; d++)
            stsf(sb + OFF_POS + (d * 128 + tid) * 4, pt[r * 3 + d] - ps[ci * 3 + d]);
    }
}

// layer-0 epilogue: +b_in +pos_rel rows, relu, pack fp16 back into A
__device__ __forceinline__ void epilogue0(uint32_t sb, int lane,
                                          int m_base, int n_base,
                                          float acc[4][8][4])
{
    float qv[3][4][2];
    #pragma unroll
    for (int mt = 0; mt < 4; mt++) {
        int m_lo = m_base + mt * 16 + (lane >> 2);
        #pragma unroll
        for (int d = 0; d < 3; d++) {
            qv[d][mt][0] = ldsf(sb + OFF_POS + (d * 128 + m_lo) * 4);
            qv[d][mt][1] = ldsf(sb + OFF_POS + (d * 128 + m_lo + 8) * 4);
        }
    }
    #pragma unroll
    for (int nt = 0; nt < 8; nt++) {
        const int n0 = n_base + nt * 8 + (lane & 3) * 2;
        float bi0 = ldsf(sb + OFF_BIAS + n0 * 4);
        float bi1 = ldsf(sb + OFF_BIAS + (n0 + 1) * 4);
        float wa0 = ldsf(sb + OFF_WP + n0 * 4);          float wa1 = ldsf(sb + OFF_WP + (n0 + 1) * 4);
        float wb0 = ldsf(sb + OFF_WP + (256 + n0) * 4);  float wb1 = ldsf(sb + OFF_WP + (256 + n0 + 1) * 4);
        float wc0 = ldsf(sb + OFF_WP + (512 + n0) * 4);  float wc1 = ldsf(sb + OFF_WP + (512 + n0 + 1) * 4);
        #pragma unroll
        for (int mt = 0; mt < 4; mt++) {
            const int m_lo = m_base + mt * 16 + (lane >> 2);
            float x00 = acc[mt][nt][0] + bi0, x01 = acc[mt][nt][1] + bi1;
            float x10 = acc[mt][nt][2] + bi0, x11 = acc[mt][nt][3] + bi1;
            x00 += qv[0][mt][0] * wa0 + qv[1][mt][0] * wb0 + qv[2][mt][0] * wc0;
            x01 += qv[0][mt][0] * wa1 + qv[1][mt][0] * wb1 + qv[2][mt][0] * wc1;
            x10 += qv[0][mt][1] * wa0 + qv[1][mt][1] * wb0 + qv[2][mt][1] * wc0;
            x11 += qv[0][mt][1] * wa1 + qv[1][mt][1] * wb1 + qv[2][mt][1] * wc1;
            x00 = fmaxf(x00, 0.f); x01 = fmaxf(x01, 0.f);
            x10 = fmaxf(x10, 0.f); x11 = fmaxf(x11, 0.f);
            sts32(sb + OFF_AH + m_lo * SA + n0 * 2, packh2(x00, x01));
            sts32(sb + OFF_AH + (m_lo + 8) * SA + n0 * 2, packh2(x10, x11));
            acc[mt][nt][0] = 0.f; acc[mt][nt][1] = 0.f;
            acc[mt][nt][2] = 0.f; acc[mt][nt][3] = 0.f;
        }
    }
}

// ---------------- main persistent kernel ------------------------------------
__global__ void __launch_bounds__(THREADS, 1)
interpnet_mma(const float* __restrict__ pos_source,
              const float* __restrict__ pos_target,
              const int*   __restrict__ row,
              const int*   __restrict__ col,
              const float* __restrict__ W_in, const float* __restrict__ b_in,
              const float* __restrict__ b1,
              float* __restrict__ out, int E, int ntiles)
{
    extern __shared__ unsigned char sm[];
    const uint32_t sb = smem_u32(sm);

    const int tid  = threadIdx.x;
    const int lane = tid & 31;
    const int wid  = tid >> 5;
    const int m_base = (wid >> 2) * 64;
    const int n_base = (wid & 3) * 64;

    // ---- one-time consts ----
    for (int i = tid; i < 512; i += THREADS) {
        int l = i >> 8, n = i & 255;
        stsf(sb + OFF_BIAS + i * 4, (l == 0) ? b_in[n] : b1[n]);
    }
    for (int i = tid; i < 768; i += THREADS) {
        int d = i >> 8, n = i & 255;
        stsf(sb + OFF_WP + i * 4, W_in[(256 + d) * 256 + n]);
    }
    if (tid < 256) stsf(sb + OFF_W2V + tid * 4, g_w2v[tid]);

    const int t0 = blockIdx.x;
    if (t0 < ntiles) {
        #pragma unroll
        for (int cc = 0; cc < 2; cc++) {
            const unsigned char* src = g_wpack + (size_t)cc * STB + tid * 16;
            uint32_t dst = sb + OFF_W + cc * STB + tid * 16;
            #pragma unroll
            for (int i = 0; i < 10; i++) cp16(dst + i * 4096, src + i * 4096);
            CP_COMMIT();
        }
        gather_tile(sb, tid, t0, E, col);
        pos_tile(sb, tid, t0, E, row, col, pos_target, pos_source);
    }

    const uint32_t aH = sb + OFF_AH + (m_base + (lane & 15)) * SA + ((lane >> 4) << 4);
    const uint32_t bB = sb + OFF_W + (n_base + (lane >> 2)) * SW + (lane & 3) * 8;
    const float bconst = g_bconst;

    int slot = 0;   // continuous ring-3 slot counter (NST=8 not divisible by 3)

    #pragma unroll 1
    for (int t = t0; t < ntiles; t += gridDim.x) {
        const bool last = (t + (int)gridDim.x >= ntiles);

        float acc[4][8][4];
        #pragma unroll
        for (int mt = 0; mt < 4; mt++)
            #pragma unroll
            for (int nt = 0; nt < 8; nt++)
                #pragma unroll
                for (int q = 0; q < 4; q++) acc[mt][nt][q] = 0.f;

        #pragma unroll 1
        for (int s = 0; s < NST; s++) {
            const int l = s >> 2;                     // layer (0 or 1)
            const int sl = s & 3;                     // stage within layer
            const uint32_t ka = (uint32_t)(sl * 128); // A byte offset

            uint32_t ah[4][4][4];                     // [k16-group][mt][frag]
            if (sl) {   // A stable within layer: hoist ALL 16 ldmatrix above wait
                #pragma unroll
                for (int kg = 0; kg < 4; kg++)
                    #pragma unroll
                    for (int mt = 0; mt < 4; mt++)
                        LDSM_X4(ah[kg][mt], aH + mt * 16 * SA + ka + kg * 32);
            }
            if (s == 0) asm volatile("cp.async.wait_group 0;" ::: "memory");
            else        asm volatile("cp.async.wait_group 1;" ::: "memory");
            __syncthreads();

            // prefetch stage s+2 into ring slot (slot+2)%3
            {
                int cn = s + 2;
                bool issue = true;
                if (cn >= NST) { cn -= NST; issue = !last; }
                if (issue) {
                    int ps = slot + 2; if (ps >= 3) ps -= 3;
                    const unsigned char* csrc = g_wpack + (size_t)cn * STB + tid * 16;
                    uint32_t cdst = sb + OFF_W + (uint32_t)ps * STB + tid * 16;
                    #pragma unroll
                    for (int i = 0; i < 10; i++) cp16(cdst + i * 4096, csrc + i * 4096);
                    CP_COMMIT();
                }
            }

            if (!sl) {
                #pragma unroll
                for (int kg = 0; kg < 4; kg++)
                    #pragma unroll
                    for (int mt = 0; mt < 4; mt++)
                        LDSM_X4(ah[kg][mt], aH + mt * 16 * SA + ka + kg * 32);
            }

            // ---- pipelined MMA sweep: 32 iters of (lds64 next | 4 MMA cur) ----
            // iteration it = kg*8 + nt ; B addr = wb + (kg>>1)*SUBCH + (kg&1)*32 + nt*(8*SW)
            {
                const uint32_t wb = bB + (uint32_t)slot * STB;
                uint32_t bc0, bc1, bn0, bn1;
                lds64(bc0, bc1, wb);
                #pragma unroll
                for (int it = 0; it < 32; it++) {
                    const int kg = it >> 3, nt = it & 7;
                    if (it < 31) {
                        const int itn = it + 1, kgn = itn >> 3, ntn = itn & 7;
                        lds64(bn0, bn1, wb + (kgn >> 1) * SUBCH + (kgn & 1) * 32
                                           + ntn * (8 * SW));
                    }
                    #pragma unroll
                    for (int mt = 0; mt < 4; mt++)
                        MMAF16(acc[mt][nt], ah[kg][mt], bc0, bc1);
                    bc0 = bn0; bc1 = bn1;
                }
            }

            if (++slot >= 3) slot = 0;

            if (sl == 3) {
                __syncthreads();                       // all A reads of layer done
                if (l == 0) epilogue0(sb, lane, m_base, n_base, acc);
            }
        }

        // ---- tile boundary: next-tile gather overlaps final epilogue ----
        const int t2 = t + (int)gridDim.x;
        if (t2 < ntiles) {
            gather_tile(sb, tid, t2, E, col);
            pos_tile(sb, tid, t2, E, row, col, pos_target, pos_source);
        }

        // final epilogue: out = relu(acc + b1) . w2v  (fp32, register-resident)
        float sfin[4][2] = {{0.f,0.f},{0.f,0.f},{0.f,0.f},{0.f,0.f}};
        #pragma unroll
        for (int nt = 0; nt < 8; nt++) {
            const int n0 = n_base + nt * 8 + (lane & 3) * 2;
            float bi0 = ldsf(sb + OFF_BIAS + (256 + n0) * 4);
            float bi1 = ldsf(sb + OFF_BIAS + (256 + n0 + 1) * 4);
            float w0  = ldsf(sb + OFF_W2V + n0 * 4);
            float w1  = ldsf(sb + OFF_W2V + (n0 + 1) * 4);
            #pragma unroll
            for (int mt = 0; mt < 4; mt++) {
                sfin[mt][0] += fmaxf(acc[mt][nt][0] + bi0, 0.f) * w0
                             + fmaxf(acc[mt][nt][1] + bi1, 0.f) * w1;
                sfin[mt][1] += fmaxf(acc[mt][nt][2] + bi0, 0.f) * w0
                             + fmaxf(acc[mt][nt][3] + bi1, 0.f) * w1;
            }
        }
        #pragma unroll
        for (int mt = 0; mt < 4; mt++) {
            float s0 = sfin[mt][0], s1 = sfin[mt][1];
            s0 += __shfl_xor_sync(0xffffffffu, s0, 1);
            s0 += __shfl_xor_sync(0xffffffffu, s0, 2);
            s1 += __shfl_xor_sync(0xffffffffu, s1, 1);
            s1 += __shfl_xor_sync(0xffffffffu, s1, 2);
            if ((lane & 3) == 0) {
                int m_lo = m_base + mt * 16 + (lane >> 2);
                stsf(sb + OFF_RED + (m_lo * 4 + (wid & 3)) * 4, s0);
                stsf(sb + OFF_RED + ((m_lo + 8) * 4 + (wid & 3)) * 4, s1);
            }
        }
        __syncthreads();
        if (tid < TILE_M) {
            float s = ldsf(sb + OFF_RED + (tid * 4 + 0) * 4)
                    + ldsf(sb + OFF_RED + (tid * 4 + 1) * 4)
                    + ldsf(sb + OFF_RED + (tid * 4 + 2) * 4)
                    + ldsf(sb + OFF_RED + (tid * 4 + 3) * 4);
            int e = t * TILE_M + tid;
            if (e < E) out[e] = s + bconst;
        }
    }
}

// ---------------- launch -----------------------------------------------------
extern "C" void kernel_launch(void* const* d_in, const int* in_sizes, int n_in,
                              void* d_out, int out_size)
{
    const float* pos_source = (const float*)d_in[0];
    const float* pos_target = (const float*)d_in[1];
    const float* latents    = (const float*)d_in[2];
    const int*   row        = (const int*)  d_in[3];
    const int*   col        = (const int*)  d_in[4];
    const float* W_in  = (const float*)d_in[5];
    const float* b_in  = (const float*)d_in[6];
    const float* W1    = (const float*)d_in[7];
    const float* b1    = (const float*)d_in[8];
    const float* W2    = (const float*)d_in[9];
    const float* b2    = (const float*)d_in[10];
    const float* W_out = (const float*)d_in[11];
    const float* b_out = (const float*)d_in[12];
    float* out = (float*)d_out;

    const int E = in_sizes[3];
    int nrows = in_sizes[2] / 256;
    if (nrows > NSRC_MAX) nrows = NSRC_MAX;

    prep_latents<<<(int)(((long)nrows * 64 + 255) / 256), 256>>>(latents, nrows);
    prep_weights<<<(NSUB * 256 * 16 + 255) / 256, 256>>>(W_in, W1);
    prep_w2v<<<257, 64>>>(W2, b2, W_out, b_out);

    int numSMs = 148;
    cudaDeviceGetAttribute(&numSMs, cudaDevAttrMultiProcessorCount, 0);

    const int ntiles = (E + TILE_M - 1) / TILE_M;
    int grid = numSMs < ntiles ? numSMs : ntiles;

    cudaFuncSetAttribute(interpnet_mma,
                         cudaFuncAttributeMaxDynamicSharedMemorySize, SMEM_TOTAL);
    interpnet_mma<<<grid, THREADS, SMEM_TOTAL>>>(
        pos_source, pos_target, row, col,
        W_in, b_in, b1, out, E, ntiles);
}